// round 15
// baseline (speedup 1.0000x reference)
#include <cuda_runtime.h>

// ---------------- problem constants ----------------
#define BB    4
#define DIM   64
#define RANK  32
#define EE    4
#define HH    256
#define WW    256
#define HWSZ  65536
#define NPIX  262144

// ---------------- device scratch ----------------
__device__ float g_gate[NPIX];
__device__ int   g_idx[NPIX];
__device__ float g_W[4 * 96 * 64];           // fused [Wq;Wkv] per expert
__device__ float g_W2[4 * 64 * 32];          // ow @ p2w per expert (proven exact in R6/R7)
__device__ float g_pre[(size_t)NPIX * 96];   // [p][0:32)=qpre, [32:96)=kvpre
__device__ float g_av [(size_t)NPIX * 64];   // [p][0:32)=attn, [32:64)=v
__device__ float g_ox [(size_t)NPIX * 64];   // m^2*(ow@x) + outb, pixel-major

// ---------------- prep: fold weight products ----------------
__global__ void k_prep(const float* __restrict__ qw,
                       const float* __restrict__ kvw,
                       const float* __restrict__ p0,
                       const float* __restrict__ p2w,
                       const float* __restrict__ ow) {
    int i = blockIdx.x * blockDim.x + threadIdx.x;     // < 32768
    if (i < 24576) {
        int e = i / 6144;
        int rem = i - e * 6144;
        int o = rem >> 6, c = rem & 63;
        const float* p0e = p0 + e * 2048;
        float acc = 0.f;
        if (o < 32) {
            const float* qe = qw + e * 1024 + o * 32;
            #pragma unroll
            for (int r = 0; r < 32; r++) acc += qe[r] * p0e[r * 64 + c];
        } else {
            const float* ke = kvw + e * 2048 + (o - 32) * 32;
            #pragma unroll
            for (int r = 0; r < 32; r++) acc += ke[r] * p0e[r * 64 + c];
        }
        g_W[i] = acc;
    } else {
        int j = i - 24576;                             // < 8192
        int e = j >> 11;
        int rem = j & 2047;
        int o = rem >> 5, r = rem & 31;
        const float* p2e = p2w + e * 2048;
        const float* owr = ow + o * 64;
        float acc = 0.f;
        #pragma unroll
        for (int c = 0; c < 64; c++) acc += owr[c] * p2e[c * 32 + r];
        g_W2[e * 2048 + o * 32 + r] = acc;
    }
}

// ---------------- AR: router + 1x1 conv + ox(ow from global/L1) ----------------
// sW: [0,24576) W | rw 24576 | rb 24832 | ob 24836 ; total 24900
#define AR_SMEM 24900
__global__ __launch_bounds__(256) void k_AR(const float* __restrict__ x,
                                            const float* __restrict__ rw,
                                            const float* __restrict__ rb,
                                            const float* __restrict__ ow,
                                            const float* __restrict__ ob) {
    extern __shared__ float sW[];
    int tid = threadIdx.x;
    for (int i = tid; i < 24576; i += 256) sW[i] = g_W[i];
    if (tid < 256) sW[24576 + tid] = rw[tid];
    if (tid < 4)   sW[24832 + tid] = rb[tid];
    if (tid < 64)  sW[24836 + tid] = ob[tid];
    __syncthreads();

    int p = blockIdx.x * 256 + tid;
    int b = p >> 16, s = p & 0xFFFF;
    const float* xb = x + ((size_t)b * DIM) * HWSZ + s;
    float xv[64];
    #pragma unroll
    for (int c = 0; c < 64; c++) xv[c] = xb[(size_t)c * HWSZ];

    const float* srw = sW + 24576;
    float l0 = sW[24832], l1 = sW[24833], l2 = sW[24834], l3 = sW[24835];
    #pragma unroll
    for (int c = 0; c < 64; c++) {
        float v = xv[c];
        l0 += srw[c] * v; l1 += srw[64 + c] * v;
        l2 += srw[128 + c] * v; l3 += srw[192 + c] * v;
    }
    float lm = l0; int am = 0;
    if (l1 > lm) { lm = l1; am = 1; }
    if (l2 > lm) { lm = l2; am = 2; }
    if (l3 > lm) { lm = l3; am = 3; }
    float m = 1.0f / (expf(l0 - lm) + expf(l1 - lm) + expf(l2 - lm) + expf(l3 - lm));
    g_gate[p] = m;
    g_idx[p]  = am;
    float m2 = m * m;

    // g_ox = m^2*(ow@x_raw) + outb ; ow read from global (16KB, L1-resident, warp-uniform)
    float* oxp = g_ox + (size_t)p * 64;
    #pragma unroll 1
    for (int og = 0; og < 16; og++) {
        float r[4];
        #pragma unroll
        for (int u = 0; u < 4; u++) {
            int o = og * 4 + u;
            const float4* wr = (const float4*)(ow + o * 64);
            float acc = 0.f;
            #pragma unroll
            for (int j = 0; j < 16; j++) {
                float4 w = __ldg(wr + j);
                acc += w.x * xv[4*j] + w.y * xv[4*j+1] + w.z * xv[4*j+2] + w.w * xv[4*j+3];
            }
            r[u] = m2 * acc + sW[24836 + o];
        }
        *(float4*)(oxp + og * 4) = make_float4(r[0], r[1], r[2], r[3]);
    }

    #pragma unroll
    for (int c = 0; c < 64; c++) xv[c] *= m;      // xv = m*x

    const float4* Wv = (const float4*)(sW + am * 6144);
    float* op = g_pre + (size_t)p * 96;
    #pragma unroll 2
    for (int og = 0; og < 24; og++) {
        float r[4];
        #pragma unroll
        for (int u = 0; u < 4; u++) {
            const float4* wr = Wv + (og * 4 + u) * 16;
            float acc = 0.f;
            #pragma unroll
            for (int j = 0; j < 16; j++) {
                float4 w = wr[j];
                acc += w.x * xv[4*j] + w.y * xv[4*j+1] + w.z * xv[4*j+2] + w.w * xv[4*j+3];
            }
            r[u] = acc;
        }
        *(float4*)(op + og * 4) = make_float4(r[0], r[1], r[2], r[3]);
    }
}

// ---------------- B: dwconv (v-channel owner-trick) + circ conv -> g_av ----------------
#define OFF_KV   0          // 196*64 = 12544
#define OFF_QT   12544      // 100*32 = 3200
#define OFF_QE   15744      // 4*2081
#define OFF_KE   24068      // 4*2081
#define OFF_OUT  32392      // 64*68
#define OFF_W7   36744      // 4*64*49
#define OFF_W3   49288      // 4*32*9
#define OFF_B7   50440      // 256
#define OFF_B3   50696      // 128
#define OFF_IDX  50824      // 196 ints
#define SMEM_B_FLOATS 51020
#define ESTRIDE  2081

__global__ __launch_bounds__(512) void k_B(const float* __restrict__ qdww,
                                           const float* __restrict__ qdwb,
                                           const float* __restrict__ kvdww,
                                           const float* __restrict__ kvdwb) {
    extern __shared__ float sm[];
    int* sIdx = (int*)(sm + OFF_IDX);
    int tid = threadIdx.x;
    int blk = blockIdx.x;
    int b = blk >> 10, sp = blk & 1023, ph = sp >> 5, pw = sp & 31;
    int y0 = ph * 8 - 3, x0 = pw * 8 - 3;

    // ---- stage ALL dw weights ----
    for (int i = tid; i < 12544; i += 512) sm[OFF_W7 + i] = kvdww[i];
    for (int i = tid; i < 1152;  i += 512) sm[OFF_W3 + i] = qdww[i];
    if (tid < 256) sm[OFF_B7 + tid] = kvdwb[tid];
    if (tid < 128) sm[OFF_B3 + tid] = qdwb[tid];

    // ---- halos + owner map ----
    for (int i = tid; i < 196; i += 512) {
        int hy = i / 14, hx = i - hy * 14;
        int gy = y0 + hy, gx = x0 + hx;
        sIdx[i] = (gy >= 0 && gy < HH && gx >= 0 && gx < WW)
                ? g_idx[b * HWSZ + gy * WW + gx] : -1;
    }
    for (int i = tid; i < 196 * 16; i += 512) {
        int px = i >> 4, v = i & 15;
        int hy = px / 14, hx = px - hy * 14;
        int gy = y0 + hy, gx = x0 + hx;
        float4 val = make_float4(0.f, 0.f, 0.f, 0.f);
        if (gy >= 0 && gy < HH && gx >= 0 && gx < WW)
            val = *(const float4*)(g_pre + ((size_t)(b * HWSZ + gy * WW + gx)) * 96 + 32 + v * 4);
        *(float4*)(sm + OFF_KV + px * 64 + v * 4) = val;
    }
    for (int i = tid; i < 100 * 8; i += 512) {
        int px = i >> 3, v = i & 7;
        int hy = px / 10, hx = px - hy * 10;
        int gy = y0 + 2 + hy, gx = x0 + 2 + hx;
        float4 val = make_float4(0.f, 0.f, 0.f, 0.f);
        if (gy >= 0 && gy < HH && gx >= 0 && gx < WW)
            val = *(const float4*)(g_pre + ((size_t)(b * HWSZ + gy * WW + gx)) * 96 + v * 4);
        *(float4*)(sm + OFF_QT + px * 32 + v * 4) = val;
    }
    __syncthreads();

    // ---- dw7 ----
    {
        int ch = tid & 63, row = tid >> 6;
        if (ch < 32) {
            // k channels: needed for ALL experts (circ conv reads owner tiles at all positions)
            for (int e = 0; e < 4; e++) {
                float bv = sm[OFF_B7 + e * 64 + ch];
                float acc[8];
                #pragma unroll
                for (int j = 0; j < 8; j++) acc[j] = bv;
                #pragma unroll
                for (int ky = 0; ky < 7; ky++) {
                    const float* inr = sm + OFF_KV + (row + ky) * 896 + ch;
                    const int*   owr = sIdx + (row + ky) * 14;
                    float me[14];
                    #pragma unroll
                    for (int xx = 0; xx < 14; xx++)
                        me[xx] = (owr[xx] == e) ? inr[xx * 64] : 0.f;
                    const float* wr = sm + OFF_W7 + (e * 64 + ch) * 49 + ky * 7;
                    #pragma unroll
                    for (int kx = 0; kx < 7; kx++) {
                        float w = wr[kx];
                        #pragma unroll
                        for (int j = 0; j < 8; j++) acc[j] += w * me[j + kx];
                    }
                }
                float* kd = sm + OFF_KE + e * ESTRIDE + ch * 65 + row * 8;
                #pragma unroll
                for (int j = 0; j < 8; j++) kd[j] = acc[j];
            }
        } else {
            // v channels: each output pixel needs only its OWNER's conv (bit-exact order)
            int eo[8];
            float accj[8];
            #pragma unroll
            for (int j = 0; j < 8; j++) {
                eo[j] = sIdx[(row + 3) * 14 + (j + 3)];
                accj[j] = sm[OFF_B7 + eo[j] * 64 + ch];
            }
            #pragma unroll
            for (int ky = 0; ky < 7; ky++) {
                const float* inr = sm + OFF_KV + (row + ky) * 896 + ch;
                const int*   owr = sIdx + (row + ky) * 14;
                float in[14]; int own[14];
                #pragma unroll
                for (int xx = 0; xx < 14; xx++) { in[xx] = inr[xx * 64]; own[xx] = owr[xx]; }
                #pragma unroll
                for (int j = 0; j < 8; j++) {
                    int e = eo[j];
                    const float* wr = sm + OFF_W7 + (e * 64 + ch) * 49 + ky * 7;
                    #pragma unroll
                    for (int kx = 0; kx < 7; kx++)
                        accj[j] += wr[kx] * ((own[j + kx] == e) ? in[j + kx] : 0.f);
                }
            }
            #pragma unroll
            for (int j = 0; j < 8; j++)
                sm[OFF_OUT + (row * 8 + j) * 68 + ch] = accj[j];
        }
    }

    // ---- dw3: all experts (q tiles needed per owner over full patch) ----
    if (tid < 256) {
        int ch = tid & 31, row = tid >> 5;
        for (int e = 0; e < 4; e++) {
            float bv = sm[OFF_B3 + e * 32 + ch];
            float acc[8];
            #pragma unroll
            for (int j = 0; j < 8; j++) acc[j] = bv;
            #pragma unroll
            for (int ky = 0; ky < 3; ky++) {
                const float* inr = sm + OFF_QT + (row + ky) * 320 + ch;
                const int*   owr = sIdx + (row + ky + 2) * 14 + 2;
                float me[10];
                #pragma unroll
                for (int xx = 0; xx < 10; xx++)
                    me[xx] = (owr[xx] == e) ? inr[xx * 32] : 0.f;
                const float* wr = sm + OFF_W3 + (e * 32 + ch) * 9 + ky * 3;
                #pragma unroll
                for (int kx = 0; kx < 3; kx++) {
                    float w = wr[kx];
                    #pragma unroll
                    for (int j = 0; j < 8; j++) acc[j] += w * me[j + kx];
                }
            }
            float* qd = sm + OFF_QE + e * ESTRIDE + ch * 65 + row * 8;
            #pragma unroll
            for (int j = 0; j < 8; j++) qd[j] = acc[j];
        }
    }
    __syncthreads();

    // ---- circular conv: 4 outputs/thread, shared row loads when owner-uniform ----
    {
        int ch = tid >> 4;
        int g4 = (tid & 15) * 4;
        int i = g4 >> 3, j0 = g4 & 7;
        int e0 = sIdx[(i + 3) * 14 + ((g4     & 7) + 3)];
        int e1 = sIdx[(i + 3) * 14 + (((g4+1) & 7) + 3)];
        int e2 = sIdx[(i + 3) * 14 + (((g4+2) & 7) + 3)];
        int e3 = sIdx[(i + 3) * 14 + (((g4+3) & 7) + 3)];
        if (e0 == e1 && e1 == e2 && e2 == e3) {
            const float* q = sm + OFF_QE + e0 * ESTRIDE + ch * 65;
            const float* k = sm + OFF_KE + e0 * ESTRIDE + ch * 65;
            float o4[4] = {0.f, 0.f, 0.f, 0.f};
            #pragma unroll
            for (int a = 0; a < 8; a++) {
                const float* ka = k + ((i - a) & 7) * 8;
                float kr[8];
                #pragma unroll
                for (int t = 0; t < 8; t++) kr[t] = ka[t];
                const float* qa = q + a * 8;
                #pragma unroll
                for (int bb = 0; bb < 8; bb++) {
                    float qv = qa[bb];
                    #pragma unroll
                    for (int jj = 0; jj < 4; jj++)
                        o4[jj] += qv * kr[(j0 + jj - bb) & 7];
                }
            }
            #pragma unroll
            for (int jj = 0; jj < 4; jj++)
                sm[OFF_OUT + (g4 + jj) * 68 + ch] = o4[jj];
        } else {
            #pragma unroll
            for (int pp = 0; pp < 4; pp++) {
                int px = g4 + pp;
                int j = px & 7;
                int e = sIdx[(i + 3) * 14 + (j + 3)];
                const float* q = sm + OFF_QE + e * ESTRIDE + ch * 65;
                const float* k = sm + OFF_KE + e * ESTRIDE + ch * 65;
                float o = 0.f;
                #pragma unroll
                for (int a = 0; a < 8; a++) {
                    const float* qa = q + a * 8;
                    const float* ka = k + ((i - a) & 7) * 8;
                    #pragma unroll
                    for (int bb = 0; bb < 8; bb++)
                        o += qa[bb] * ka[(j - bb) & 7];
                }
                sm[OFF_OUT + px * 68 + ch] = o;
            }
        }
    }
    __syncthreads();

    // ---- dense write of attn+v (pixel-major) ----
    for (int i = tid; i < 64 * 16; i += 512) {
        int px = i >> 4, v = i & 15;
        int gi = px >> 3, gj = px & 7;
        size_t gp = (size_t)b * HWSZ + (ph * 8 + gi) * WW + (pw * 8 + gj);
        *(float4*)(g_av + gp * 64 + v * 4) = *(float4*)(sm + OFF_OUT + px * 68 + v * 4);
    }
}

// ---------------- DO: LN, *v, fp, silu gate, W2@bg + g_ox ----------------
// per-expert 5216: fp 1024 | p1 2048 | W2 2048 | fpb 32 | lnw 32 | lnb 32
#define DO_SMEM 20864
__global__ __launch_bounds__(256) void k_DO(const float* __restrict__ sh,
                                            const float* __restrict__ fpw,
                                            const float* __restrict__ fpb,
                                            const float* __restrict__ p1w,
                                            const float* __restrict__ lnw,
                                            const float* __restrict__ lnb,
                                            float* __restrict__ out) {
    extern __shared__ float smd[];
    int tid = threadIdx.x;
    for (int i = tid; i < 4096; i += 256) smd[(i >> 10) * 5216 + (i & 1023)] = fpw[i];
    for (int i = tid; i < 8192; i += 256) smd[(i >> 11) * 5216 + 1024 + (i & 2047)] = p1w[i];
    for (int i = tid; i < 8192; i += 256) smd[(i >> 11) * 5216 + 3072 + (i & 2047)] = g_W2[i];
    if (tid < 128) {
        smd[(tid >> 5) * 5216 + 5120 + (tid & 31)] = fpb[tid];
        smd[(tid >> 5) * 5216 + 5152 + (tid & 31)] = lnw[tid];
        smd[(tid >> 5) * 5216 + 5184 + (tid & 31)] = lnb[tid];
    }
    __syncthreads();

    int p = blockIdx.x * 256 + tid;
    int b = p >> 16, s = p & 0xFFFF;
    int e = g_idx[p];
    float m = g_gate[p];
    const float* base_ = smd + e * 5216;
    const float* s_fp  = base_;
    const float* s_p1  = base_ + 1024;
    const float* s_W2  = base_ + 3072;
    const float* s_fpb = base_ + 5120;
    const float* s_lnw = base_ + 5152;
    const float* s_lnb = base_ + 5184;

    // 1. gate dots from shared path
    float gg[32];
    {
        float shv[64];
        const float* shb = sh + ((size_t)b * DIM) * HWSZ + s;
        #pragma unroll
        for (int c = 0; c < 64; c++) shv[c] = shb[(size_t)c * HWSZ];
        #pragma unroll 2
        for (int o = 0; o < 32; o++) {
            const float4* pr = (const float4*)(s_p1 + o * 64);
            float g = 0.f;
            #pragma unroll
            for (int j = 0; j < 16; j++) {
                float4 w = pr[j];
                g += w.x * shv[4*j] + w.y * shv[4*j+1] + w.z * shv[4*j+2] + w.w * shv[4*j+3];
            }
            gg[o] = g;
        }
    }

    // 2. LN(attn) * v — two-pass (centered) variance
    const float* av = g_av + (size_t)p * 64;
    float t[32], vv[32];
    #pragma unroll
    for (int j = 0; j < 8; j++) {
        float4 a4 = *(const float4*)(av + j * 4);
        t[4*j] = a4.x; t[4*j+1] = a4.y; t[4*j+2] = a4.z; t[4*j+3] = a4.w;
        float4 v4 = *(const float4*)(av + 32 + j * 4);
        vv[4*j] = v4.x; vv[4*j+1] = v4.y; vv[4*j+2] = v4.z; vv[4*j+3] = v4.w;
    }
    float sum = 0.f;
    #pragma unroll
    for (int r = 0; r < 32; r++) sum += t[r];
    float mean = sum * (1.f / 32.f);
    float sq = 0.f;
    #pragma unroll
    for (int r = 0; r < 32; r++) { float d = t[r] - mean; sq += d * d; }
    float var = sq * (1.f / 32.f);
    float inv = rsqrtf(var + 1e-5f);
    #pragma unroll
    for (int r = 0; r < 32; r++)
        t[r] = ((t[r] - mean) * inv * s_lnw[r] + s_lnb[r]) * vv[r];

    // 3. body * silu gate
    float bg[32];
    #pragma unroll 2
    for (int o = 0; o < 32; o++) {
        const float4* fr = (const float4*)(s_fp + o * 32);
        float acc = s_fpb[o];
        #pragma unroll
        for (int j = 0; j < 8; j++) {
            float4 w = fr[j];
            acc += w.x * t[4*j] + w.y * t[4*j+1] + w.z * t[4*j+2] + w.w * t[4*j+3];
        }
        float z = m * gg[o];
        float sg = z / (1.f + expf(-z));
        bg[o] = acc * sg;
    }

    // 4. out = m*(W2e@bg) + g_ox   (g_ox = m^2*(ow@x)+outb)
    const float4* oxp4 = (const float4*)(g_ox + (size_t)p * 64);
    float* ob_ = out + ((size_t)b * DIM) * HWSZ + s;
    #pragma unroll 2
    for (int og = 0; og < 16; og++) {
        float4 ox4 = oxp4[og];
        #pragma unroll
        for (int u = 0; u < 4; u++) {
            int o = og * 4 + u;
            const float4* wr = (const float4*)(s_W2 + o * 32);
            float acc = 0.f;
            #pragma unroll
            for (int j = 0; j < 8; j++) {
                float4 w = wr[j];
                acc += w.x * bg[4*j] + w.y * bg[4*j+1] + w.z * bg[4*j+2] + w.w * bg[4*j+3];
            }
            float oxo = (u == 0) ? ox4.x : (u == 1) ? ox4.y : (u == 2) ? ox4.z : ox4.w;
            ob_[(size_t)o * HWSZ] = m * acc + oxo;
        }
    }
}

// ---------------- launch ----------------
extern "C" void kernel_launch(void* const* d_in, const int* in_sizes, int n_in,
                              void* d_out, int out_size) {
    const float* x     = (const float*)d_in[0];
    const float* sh    = (const float*)d_in[1];
    const float* rw    = (const float*)d_in[2];
    const float* rb    = (const float*)d_in[3];
    const float* p0w   = (const float*)d_in[4];
    const float* p1w   = (const float*)d_in[5];
    const float* p2w   = (const float*)d_in[6];
    const float* qw    = (const float*)d_in[7];
    const float* qdww  = (const float*)d_in[8];
    const float* qdwb  = (const float*)d_in[9];
    const float* kvw   = (const float*)d_in[10];
    const float* kvdww = (const float*)d_in[11];
    const float* kvdwb = (const float*)d_in[12];
    const float* lnw   = (const float*)d_in[13];
    const float* lnb   = (const float*)d_in[14];
    const float* fpw   = (const float*)d_in[15];
    const float* fpb   = (const float*)d_in[16];
    const float* outw  = (const float*)d_in[17];
    const float* outb  = (const float*)d_in[18];
    float* out = (float*)d_out;

    cudaFuncSetAttribute(k_AR, cudaFuncAttributeMaxDynamicSharedMemorySize, AR_SMEM * 4);
    cudaFuncSetAttribute(k_B,  cudaFuncAttributeMaxDynamicSharedMemorySize, SMEM_B_FLOATS * 4);
    cudaFuncSetAttribute(k_DO, cudaFuncAttributeMaxDynamicSharedMemorySize, DO_SMEM * 4);

    k_prep<<<128, 256>>>(qw, kvw, p0w, p2w, outw);
    k_AR<<<NPIX / 256, 256, AR_SMEM * 4>>>(x, rw, rb, outw, outb);
    k_B<<<BB * 1024, 512, SMEM_B_FLOATS * 4>>>(qdww, qdwb, kvdww, kvdwb);
    k_DO<<<NPIX / 256, 256, DO_SMEM * 4>>>(sh, fpw, fpb, p1w, lnw, lnb, out);
}

// round 17
// speedup vs baseline: 1.5116x; 1.5116x over previous
#include <cuda_runtime.h>
#include <cuda_bf16.h>
#include <cstdint>

typedef unsigned int u32;

// ---------------- problem constants ----------------
#define BB    4
#define DIM   64
#define RANK  32
#define EE    4
#define HH    256
#define WW    256
#define HWSZ  65536
#define NPIX  262144

// ---------------- device scratch ----------------
__device__ float g_gate[NPIX];
__device__ int   g_idx[NPIX];
__device__ __nv_bfloat16 g_Wh[24576];               // fused [Wq;Wkv] per expert, bf16
__device__ __nv_bfloat16 g_EWh[22528];              // epilogue weights, padded rows, bf16
__device__ __nv_bfloat16 g_W7th[12544];             // dw7 weights transposed [e][tap][ch]
__device__ __nv_bfloat16 g_W3th[1152];              // dw3 weights transposed [e][tap][ch]
__device__ __nv_bfloat16 g_preh[(size_t)NPIX * 96]; // [p][0:32)=qpre, [32:96)=kvpre

__device__ __forceinline__ u32 packbf(float a, float b) {
    __nv_bfloat162 h = __floats2bfloat162_rn(a, b);
    return *(u32*)&h;
}
__device__ __forceinline__ float2 upbf(u32 u) {
    __nv_bfloat162 h = *(__nv_bfloat162*)&u;
    return __bfloat1622float2(h);
}
__device__ __forceinline__ float h2f(__nv_bfloat16 h) { return __bfloat162float(h); }

// ---------------- prep: fold + convert + transpose all weights ----------------
__global__ void k_prep(const float* __restrict__ qw,
                       const float* __restrict__ kvw,
                       const float* __restrict__ p0,
                       const float* __restrict__ fpw,
                       const float* __restrict__ p1w,
                       const float* __restrict__ p2w,
                       const float* __restrict__ qdww,
                       const float* __restrict__ kvdww) {
    int i = blockIdx.x * blockDim.x + threadIdx.x;
    if (i < 24576) {
        int e = i / 6144;
        int rem = i - e * 6144;
        int o = rem >> 6, c = rem & 63;
        const float* p0e = p0 + e * 2048;
        float acc = 0.f;
        if (o < 32) {
            const float* qe = qw + e * 1024 + o * 32;
            #pragma unroll
            for (int r = 0; r < 32; r++) acc += qe[r] * p0e[r * 64 + c];
        } else {
            const float* ke = kvw + e * 2048 + (o - 32) * 32;
            #pragma unroll
            for (int r = 0; r < 32; r++) acc += ke[r] * p0e[r * 64 + c];
        }
        g_Wh[i] = __float2bfloat16(acc);
    } else if (i < 47104) {
        int j = i - 24576;
        int e = j / 5632, r = j - e * 5632;
        float val = 0.f;
        if (r < 1152) {
            int o = r / 36, c = r - o * 36;
            if (c < 32) val = fpw[e * 1024 + o * 32 + c];
        } else if (r < 3328) {
            int rr = r - 1152;
            int o = rr / 68, c = rr - o * 68;
            if (c < 64) val = p1w[e * 2048 + o * 64 + c];
        } else {
            int rr = r - 3328;
            int o = rr / 36, c = rr - o * 36;
            if (c < 32) val = p2w[e * 2048 + o * 32 + c];
        }
        g_EWh[j] = __float2bfloat16(val);
    } else if (i < 59648) {
        int j = i - 47104;
        int e = j / 3136, rr = j - e * 3136;
        int t = rr >> 6, ch = rr & 63;
        g_W7th[j] = __float2bfloat16(kvdww[e * 3136 + ch * 49 + t]);
    } else if (i < 60800) {
        int j = i - 59648;
        int e = j / 288, rr = j - e * 288;
        int t = rr >> 5, ch = rr & 31;
        g_W3th[j] = __float2bfloat16(qdww[e * 288 + ch * 9 + t]);
    }
}

// ---------------- AR: router (fp32 exact) + bf16 1x1 conv -> g_preh ----------------
#define AR_SMEM_BYTES 50192
__global__ __launch_bounds__(256) void k_AR(const float* __restrict__ x,
                                            const float* __restrict__ rw,
                                            const float* __restrict__ rb) {
    extern __shared__ float sW[];
    u32* sWu = (u32*)sW;
    int tid = threadIdx.x;
    const u32* gW = (const u32*)g_Wh;
    for (int i = tid; i < 12288; i += 256) sWu[i] = gW[i];
    if (tid < 256) sW[12288 + tid] = rw[tid];
    if (tid < 4)   sW[12544 + tid] = rb[tid];
    __syncthreads();

    int p = blockIdx.x * 256 + tid;
    int b = p >> 16, s = p & 0xFFFF;
    const float* xb = x + ((size_t)b * DIM) * HWSZ + s;
    float xv[64];
    #pragma unroll
    for (int c = 0; c < 64; c++) xv[c] = xb[(size_t)c * HWSZ];

    const float* srw = sW + 12288;
    float l0 = sW[12544], l1 = sW[12545], l2 = sW[12546], l3 = sW[12547];
    #pragma unroll
    for (int c = 0; c < 64; c++) {
        float v = xv[c];
        l0 += srw[c] * v; l1 += srw[64 + c] * v;
        l2 += srw[128 + c] * v; l3 += srw[192 + c] * v;
    }
    float lm = l0; int am = 0;
    if (l1 > lm) { lm = l1; am = 1; }
    if (l2 > lm) { lm = l2; am = 2; }
    if (l3 > lm) { lm = l3; am = 3; }
    float m = 1.0f / (expf(l0 - lm) + expf(l1 - lm) + expf(l2 - lm) + expf(l3 - lm));
    g_gate[p] = m;
    g_idx[p]  = am;

    #pragma unroll
    for (int c = 0; c < 64; c++) xv[c] *= m;      // xv = m*x

    const u32* Wvu = sWu + am * 3072;             // 6144 bf16 per expert
    u32* op = (u32*)(g_preh + (size_t)p * 96);
    #pragma unroll 2
    for (int og = 0; og < 24; og++) {
        float r[4];
        #pragma unroll
        for (int u = 0; u < 4; u++) {
            const u32* wr = Wvu + (og * 4 + u) * 32;
            float acc = 0.f;
            #pragma unroll
            for (int j = 0; j < 32; j++) {
                float2 f = upbf(wr[j]);
                acc += f.x * xv[2*j] + f.y * xv[2*j+1];
            }
            r[u] = acc;
        }
        op[og * 2]     = packbf(r[0], r[1]);
        op[og * 2 + 1] = packbf(r[2], r[3]);
    }
}

// ---------------- k_B byte-offset layout ----------------
// phase 1 (dw+circ):
#define B_KV   0         // bf16 196*64
#define B_QT   25088     // bf16 100*32
#define B_QE   31488     // bf16 4*2114 (expert stride 2114, ch stride 66)
#define B_KE   48400     // bf16 4*2114
#define B_OUT  65312     // f32 64*68  (live across phases)
#define B_B7   82720     // f32 256
#define B_B3   83744     // f32 128
#define B_IDX  84256     // int 196   (live across phases)
#define B_W7T  85040     // bf16 12544
#define B_W3T  110128    // bf16 1152
#define SMEM_B_BYTES 112432
// phase 2 (epilogue, aliases dead regions):
#define B_EX   0         // f32 64*68 (x)
#define B_EW   17408     // bf16 4*5632 (fp 32x36 | p1 32x68 | p2 64x36)
#define B_SH   85040     // bf16 64*68
#define B_BG   93744     // f32 64*40
#define B_GATE 103984    // f32 64
#define B_EIX  104240    // int 64
#define B_OB   104496    // f32 64
#define B_BIAS 104752    // f32 4*96 (fpb|lnw|lnb)

__global__ __launch_bounds__(512, 2) void k_B(const float* __restrict__ qdwb,
                                              const float* __restrict__ kvdwb,
                                              const float* __restrict__ x,
                                              const float* __restrict__ sh,
                                              const float* __restrict__ fpb,
                                              const float* __restrict__ lnw,
                                              const float* __restrict__ lnb,
                                              const float* __restrict__ ow,
                                              const float* __restrict__ ob,
                                              float* __restrict__ out) {
    extern __shared__ float smf[];
    __nv_bfloat16* smh = (__nv_bfloat16*)smf;
    u32* smu = (u32*)smf;
    int* sIdx = (int*)(smf + B_IDX / 4);
    int tid = threadIdx.x;
    int blk = blockIdx.x;
    int b = blk >> 10, sp = blk & 1023, ph = sp >> 5, pw = sp & 31;
    int y0 = ph * 8 - 3, x0 = pw * 8 - 3;

    // ---- phase 1: staging ----
    for (int i = tid; i < 6272; i += 512) smu[B_W7T/4 + i] = ((const u32*)g_W7th)[i];
    for (int i = tid; i < 576;  i += 512) smu[B_W3T/4 + i] = ((const u32*)g_W3th)[i];
    if (tid < 256) smf[B_B7/4 + tid] = kvdwb[tid];
    if (tid < 128) smf[B_B3/4 + tid] = qdwb[tid];
    for (int i = tid; i < 196; i += 512) {
        int hy = i / 14, hx = i - hy * 14;
        int gy = y0 + hy, gx = x0 + hx;
        sIdx[i] = (gy >= 0 && gy < HH && gx >= 0 && gx < WW)
                ? g_idx[b * HWSZ + gy * WW + gx] : -1;
    }
    for (int i = tid; i < 196 * 8; i += 512) {     // kv halo: 8x uint4 per px
        int px = i >> 3, v = i & 7;
        int hy = px / 14, hx = px - hy * 14;
        int gy = y0 + hy, gx = x0 + hx;
        uint4 val = make_uint4(0, 0, 0, 0);
        if (gy >= 0 && gy < HH && gx >= 0 && gx < WW)
            val = *(const uint4*)(g_preh + ((size_t)(b * HWSZ + gy * WW + gx)) * 96 + 32 + v * 8);
        *(uint4*)(smh + px * 64 + v * 8) = val;
    }
    for (int i = tid; i < 100 * 4; i += 512) {     // q halo: 4x uint4 per px
        int px = i >> 2, v = i & 3;
        int hy = px / 10, hx = px - hy * 10;
        int gy = y0 + 2 + hy, gx = x0 + 2 + hx;
        uint4 val = make_uint4(0, 0, 0, 0);
        if (gy >= 0 && gy < HH && gx >= 0 && gx < WW)
            val = *(const uint4*)(g_preh + ((size_t)(b * HWSZ + gy * WW + gx)) * 96 + v * 8);
        *(uint4*)(smh + B_QT/2 + px * 32 + v * 8) = val;
    }
    __syncthreads();

    // ---- dw7 ----
    {
        int ch = tid & 63, row = tid >> 6;
        const __nv_bfloat16* W7 = smh + B_W7T/2;
        if (ch < 32) {
            // k channels: all 4 experts
            #pragma unroll 1
            for (int e = 0; e < 4; e++) {
                float bv = smf[B_B7/4 + e * 64 + ch];
                float acc[8];
                #pragma unroll
                for (int j = 0; j < 8; j++) acc[j] = bv;
                #pragma unroll
                for (int ky = 0; ky < 7; ky++) {
                    const __nv_bfloat16* inr = smh + ((row + ky) * 14) * 64 + ch;
                    const int* owr = sIdx + (row + ky) * 14;
                    float in[14]; int own[14];
                    #pragma unroll
                    for (int xx = 0; xx < 14; xx++) { in[xx] = h2f(inr[xx * 64]); own[xx] = owr[xx]; }
                    const __nv_bfloat16* wr = W7 + (e * 49 + ky * 7) * 64 + ch;
                    #pragma unroll
                    for (int kx = 0; kx < 7; kx++) {
                        float w = h2f(wr[kx * 64]);
                        #pragma unroll
                        for (int j = 0; j < 8; j++)
                            acc[j] += w * ((own[j + kx] == e) ? in[j + kx] : 0.f);
                    }
                }
                u32* kd = smu + B_KE/4 + e * 1057 + ch * 33 + row * 4;
                #pragma unroll
                for (int jj = 0; jj < 4; jj++) kd[jj] = packbf(acc[2*jj], acc[2*jj+1]);
            }
        } else {
            // v channels: owner-only conv
            int eo[8]; float acc[8];
            #pragma unroll
            for (int j = 0; j < 8; j++) {
                eo[j] = sIdx[(row + 3) * 14 + j + 3];
                acc[j] = smf[B_B7/4 + eo[j] * 64 + ch];
            }
            #pragma unroll
            for (int ky = 0; ky < 7; ky++) {
                const __nv_bfloat16* inr = smh + ((row + ky) * 14) * 64 + ch;
                const int* owr = sIdx + (row + ky) * 14;
                float in[14]; int own[14];
                #pragma unroll
                for (int xx = 0; xx < 14; xx++) { in[xx] = h2f(inr[xx * 64]); own[xx] = owr[xx]; }
                #pragma unroll
                for (int j = 0; j < 8; j++) {
                    int e = eo[j];
                    const __nv_bfloat16* wr = W7 + (e * 49 + ky * 7) * 64 + ch;
                    #pragma unroll
                    for (int kx = 0; kx < 7; kx++)
                        acc[j] += h2f(wr[kx * 64]) * ((own[j + kx] == e) ? in[j + kx] : 0.f);
                }
            }
            #pragma unroll
            for (int j = 0; j < 8; j++)
                smf[B_OUT/4 + (row * 8 + j) * 68 + ch] = acc[j];
        }
    }

    // ---- dw3: all experts ----
    if (tid < 256) {
        int ch = tid & 31, row = tid >> 5;
        const __nv_bfloat16* W3 = smh + B_W3T/2;
        const __nv_bfloat16* qt = smh + B_QT/2;
        #pragma unroll 1
        for (int e = 0; e < 4; e++) {
            float bv = smf[B_B3/4 + e * 32 + ch];
            float acc[8];
            #pragma unroll
            for (int j = 0; j < 8; j++) acc[j] = bv;
            #pragma unroll
            for (int ky = 0; ky < 3; ky++) {
                const __nv_bfloat16* inr = qt + ((row + ky) * 10) * 32 + ch;
                const int* owr = sIdx + (row + ky + 2) * 14 + 2;
                float in[10]; int own[10];
                #pragma unroll
                for (int xx = 0; xx < 10; xx++) { in[xx] = h2f(inr[xx * 32]); own[xx] = owr[xx]; }
                const __nv_bfloat16* wr = W3 + (e * 9 + ky * 3) * 32 + ch;
                #pragma unroll
                for (int kx = 0; kx < 3; kx++) {
                    float w = h2f(wr[kx * 32]);
                    #pragma unroll
                    for (int j = 0; j < 8; j++)
                        acc[j] += w * ((own[j + kx] == e) ? in[j + kx] : 0.f);
                }
            }
            u32* qd = smu + B_QE/4 + e * 1057 + ch * 33 + row * 4;
            #pragma unroll
            for (int jj = 0; jj < 4; jj++) qd[jj] = packbf(acc[2*jj], acc[2*jj+1]);
        }
    }
    __syncthreads();

    // ---- circular conv per pixel with owner's q,k -> OUT ch 0..31 ----
    {
        int ch = tid >> 4;
        int g4 = (tid & 15) * 4;
        int i = g4 >> 3, j0 = g4 & 7;
        int base = (i + 3) * 14 + 3;
        int e0 = sIdx[base + j0], e1 = sIdx[base + j0 + 1];
        int e2 = sIdx[base + j0 + 2], e3 = sIdx[base + j0 + 3];
        if (e0 == e1 && e1 == e2 && e2 == e3) {
            const u32* qb = smu + B_QE/4 + e0 * 1057 + ch * 33;
            const u32* kb = smu + B_KE/4 + e0 * 1057 + ch * 33;
            float o4[4] = {0.f, 0.f, 0.f, 0.f};
            #pragma unroll
            for (int a = 0; a < 8; a++) {
                int ia = (i - a) & 7;
                float kr[8], qa[8];
                #pragma unroll
                for (int t = 0; t < 4; t++) {
                    float2 f = upbf(kb[ia * 4 + t]); kr[2*t] = f.x; kr[2*t+1] = f.y;
                    float2 g = upbf(qb[a * 4 + t]);  qa[2*t] = g.x; qa[2*t+1] = g.y;
                }
                #pragma unroll
                for (int bb = 0; bb < 8; bb++) {
                    float qv = qa[bb];
                    #pragma unroll
                    for (int jj = 0; jj < 4; jj++)
                        o4[jj] += qv * kr[(j0 + jj - bb) & 7];
                }
            }
            #pragma unroll
            for (int jj = 0; jj < 4; jj++)
                smf[B_OUT/4 + (g4 + jj) * 68 + ch] = o4[jj];
        } else {
            #pragma unroll 1
            for (int pp = 0; pp < 4; pp++) {
                int px = g4 + pp;
                int j = px & 7;
                int e = sIdx[base + j];
                const __nv_bfloat16* q = smh + B_QE/2 + e * 2114 + ch * 66;
                const __nv_bfloat16* k = smh + B_KE/2 + e * 2114 + ch * 66;
                float o = 0.f;
                #pragma unroll
                for (int a = 0; a < 8; a++) {
                    const __nv_bfloat16* qa = q + a * 8;
                    const __nv_bfloat16* ka = k + ((i - a) & 7) * 8;
                    #pragma unroll
                    for (int bb = 0; bb < 8; bb++)
                        o += h2f(qa[bb]) * h2f(ka[(j - bb) & 7]);
                }
                smf[B_OUT/4 + px * 68 + ch] = o;
            }
        }
    }
    __syncthreads();   // dw/circ regions dead except OUT / IDX

    // ---- phase 2 staging: epilogue weights + sh(bf16) + x(f32) + gate/eix/ob/biases ----
    for (int i = tid; i < 11264; i += 512) smu[B_EW/4 + i] = ((const u32*)g_EWh)[i];
    for (int i = tid; i < 4096; i += 512) {
        int px = i & 63, c = i >> 6;
        int gy = ph * 8 + (px >> 3), gx = pw * 8 + (px & 7);
        size_t goff = (((size_t)(b * 64 + c)) << 16) + gy * WW + gx;
        smh[B_SH/2 + px * 68 + c] = __float2bfloat16(sh[goff]);
        smf[B_EX/4 + px * 68 + c] = x[goff];
    }
    if (tid < 64) {
        smf[B_OB/4 + tid] = ob[tid];
        int gy = ph * 8 + (tid >> 3), gx = pw * 8 + (tid & 7);
        smf[B_GATE/4 + tid] = g_gate[b * HWSZ + gy * WW + gx];
        ((int*)(smf + B_EIX/4))[tid] = sIdx[((tid >> 3) + 3) * 14 + (tid & 7) + 3];
    }
    if (tid < 128) {
        int e = tid >> 5, r = tid & 31;
        smf[B_BIAS/4 + e * 96 + r]      = fpb[e * 32 + r];
        smf[B_BIAS/4 + e * 96 + 32 + r] = lnw[e * 32 + r];
        smf[B_BIAS/4 + e * 96 + 64 + r] = lnb[e * 32 + r];
    }
    __syncthreads();

    int px = tid >> 3, r = tid & 7;
    int e  = ((int*)(smf + B_EIX/4))[px];
    float m = smf[B_GATE/4 + px];

    // ---- LN(attn)*v in place (two-pass variance, width-8 shfl) ----
    {
        const float* lw = smf + B_BIAS/4 + e * 96 + 32;
        const float* lb = lw + 32;
        float4 a4 = *(float4*)(smf + B_OUT/4 + px * 68 + r * 4);
        float4 v4 = *(float4*)(smf + B_OUT/4 + px * 68 + 32 + r * 4);
        float sum = a4.x + a4.y + a4.z + a4.w;
        #pragma unroll
        for (int off = 1; off < 8; off <<= 1)
            sum += __shfl_xor_sync(0xffffffffu, sum, off, 8);
        float mean = sum * (1.f / 32.f);
        float dx = a4.x - mean, dy = a4.y - mean, dz = a4.z - mean, dw = a4.w - mean;
        float sq = dx*dx + dy*dy + dz*dz + dw*dw;
        #pragma unroll
        for (int off = 1; off < 8; off <<= 1)
            sq += __shfl_xor_sync(0xffffffffu, sq, off, 8);
        float inv = rsqrtf(sq * (1.f / 32.f) + 1e-5f);
        float4 t4;
        t4.x = (dx * inv * lw[r*4    ] + lb[r*4    ]) * v4.x;
        t4.y = (dy * inv * lw[r*4 + 1] + lb[r*4 + 1]) * v4.y;
        t4.z = (dz * inv * lw[r*4 + 2] + lb[r*4 + 2]) * v4.z;
        t4.w = (dw * inv * lw[r*4 + 3] + lb[r*4 + 3]) * v4.w;
        *(float4*)(smf + B_OUT/4 + px * 68 + r * 4) = t4;
    }
    __syncthreads();

    // ---- bg = (fp@t + fpb) * silu(m * (p1@sh)) ----
    {
        const u32* ew = smu + B_EW/4 + e * 2816;
        float tv[32];
        #pragma unroll
        for (int j = 0; j < 8; j++) {
            float4 t4 = ((float4*)(smf + B_OUT/4 + px * 68))[j];
            tv[4*j] = t4.x; tv[4*j+1] = t4.y; tv[4*j+2] = t4.z; tv[4*j+3] = t4.w;
        }
        const u32* sp = smu + B_SH/4 + px * 34;
        #pragma unroll
        for (int oo = 0; oo < 4; oo++) {
            int o = r + oo * 8;
            const u32* fr = ew + o * 18;
            float facc = smf[B_BIAS/4 + e * 96 + o];
            #pragma unroll
            for (int j = 0; j < 16; j++) {
                float2 f = upbf(fr[j]);
                facc += f.x * tv[2*j] + f.y * tv[2*j+1];
            }
            const u32* pr = ew + 576 + o * 34;
            float gg = 0.f;
            #pragma unroll
            for (int j = 0; j < 32; j++) {
                float2 w = upbf(pr[j]); float2 s = upbf(sp[j]);
                gg += w.x * s.x + w.y * s.y;
            }
            float z = m * gg;
            float sg = z / (1.f + expf(-z));
            smf[B_BG/4 + px * 40 + o] = facc * sg;
        }
    }
    __syncthreads();

    // ---- comb = m*(p2@bg) + m^2*x -> OUT ----
    {
        float m2 = m * m;
        const u32* ew = smu + B_EW/4 + e * 2816;
        float bgv[32];
        #pragma unroll
        for (int j = 0; j < 8; j++) {
            float4 b4 = ((float4*)(smf + B_BG/4 + px * 40))[j];
            bgv[4*j] = b4.x; bgv[4*j+1] = b4.y; bgv[4*j+2] = b4.z; bgv[4*j+3] = b4.w;
        }
        #pragma unroll
        for (int oo = 0; oo < 8; oo++) {
            int o = r + oo * 8;
            const u32* pr = ew + 1664 + o * 18;
            float acc = 0.f;
            #pragma unroll
            for (int j = 0; j < 16; j++) {
                float2 f = upbf(pr[j]);
                acc += f.x * bgv[2*j] + f.y * bgv[2*j+1];
            }
            smf[B_OUT/4 + px * 68 + o] = m * acc + m2 * smf[B_EX/4 + px * 68 + o];
        }
    }
    __syncthreads();

    // ---- out = ow@comb + outb (fp32 exact, warp-uniform ldg rows) -> EX ----
    {
        int qx = tid & 63;
        int o0 = tid >> 6;
        const float4* cv = (const float4*)(smf + B_OUT/4 + qx * 68);
        #pragma unroll 1
        for (int oo = 0; oo < 8; oo++) {
            int o = o0 + oo * 8;
            const float4* wr = (const float4*)(ow + o * 64);
            float acc = smf[B_OB/4 + o];
            #pragma unroll
            for (int j = 0; j < 16; j++) {
                float4 w = __ldg(wr + j);
                float4 c = cv[j];
                acc += w.x * c.x + w.y * c.y + w.z * c.z + w.w * c.w;
            }
            smf[B_EX/4 + qx * 68 + o] = acc;
        }
    }
    __syncthreads();

    // ---- coalesced planar write-out ----
    for (int i = tid; i < 4096; i += 512) {
        int qx = i & 63, o = i >> 6;
        int gy = ph * 8 + (qx >> 3), gx = pw * 8 + (qx & 7);
        out[(((size_t)(b * 64 + o)) << 16) + gy * WW + gx] = smf[B_EX/4 + qx * 68 + o];
    }
}

// ---------------- launch ----------------
extern "C" void kernel_launch(void* const* d_in, const int* in_sizes, int n_in,
                              void* d_out, int out_size) {
    const float* x     = (const float*)d_in[0];
    const float* sh    = (const float*)d_in[1];
    const float* rw    = (const float*)d_in[2];
    const float* rb    = (const float*)d_in[3];
    const float* p0w   = (const float*)d_in[4];
    const float* p1w   = (const float*)d_in[5];
    const float* p2w   = (const float*)d_in[6];
    const float* qw    = (const float*)d_in[7];
    const float* qdww  = (const float*)d_in[8];
    const float* qdwb  = (const float*)d_in[9];
    const float* kvw   = (const float*)d_in[10];
    const float* kvdww = (const float*)d_in[11];
    const float* kvdwb = (const float*)d_in[12];
    const float* lnw   = (const float*)d_in[13];
    const float* lnb   = (const float*)d_in[14];
    const float* fpw   = (const float*)d_in[15];
    const float* fpb   = (const float*)d_in[16];
    const float* outw  = (const float*)d_in[17];
    const float* outb  = (const float*)d_in[18];
    float* out = (float*)d_out;

    cudaFuncSetAttribute(k_AR, cudaFuncAttributeMaxDynamicSharedMemorySize, AR_SMEM_BYTES);
    cudaFuncSetAttribute(k_B,  cudaFuncAttributeMaxDynamicSharedMemorySize, SMEM_B_BYTES);

    k_prep<<<238, 256>>>(qw, kvw, p0w, fpw, p1w, p2w, qdww, kvdww);
    k_AR<<<NPIX / 256, 256, AR_SMEM_BYTES>>>(x, rw, rb);
    k_B<<<BB * 1024, 512, SMEM_B_BYTES>>>(qdwb, kvdwb, x, sh, fpb, lnw, lnb,
                                          outw, outb, out);
}